// round 4
// baseline (speedup 1.0000x reference)
#include <cuda_runtime.h>
#include <math.h>

#define L_   2048
#define NB_  4
#define E_   512
#define H_   8
#define D_   64
#define EPS_ 1e-6f

typedef unsigned long long ull;

// ---------------- scratch (static __device__, no allocations) ----------------
__device__ float g_q[(size_t)NB_ * H_ * L_ * D_];        // 16 MB
__device__ float g_k[(size_t)NB_ * H_ * L_ * D_];        // 16 MB
__device__ float g_vp[(size_t)NB_ * H_ * L_ * D_];       // 16 MB  max(v+shift,eps)^p
__device__ float g_scores[(size_t)NB_ * H_ * L_ * L_];   // 512 MB  exp(q.k/8), unnormalized
__device__ float g_oh[(size_t)L_ * NB_ * E_];            // 16 MB  GeM-inverted heads

__device__ __forceinline__ float lo2(ull u) { return __uint_as_float((unsigned)u); }
__device__ __forceinline__ float hi2(ull u) { return __uint_as_float((unsigned)(u >> 32)); }

// packed f32x2 fma / add (ptxas never emits these from C++)
#define FMA2(d, a, b) asm("fma.rn.f32x2 %0, %1, %2, %0;" : "+l"(d) : "l"(a), "l"(b))
#define ADD2(d, a)    asm("add.rn.f32x2 %0, %1, %0;"     : "+l"(d) : "l"(a))

// MODE: 0=Q proj, 1=K proj, 2=V proj(+GeM fwd pow), 3=scores exp(qk/8), 4=out proj
// C[m][j] = sum_k A[m][k] * B[j][k]  (TN, row-major), FMA2 mainloop.
// B is stored DUPLICATED in smem: Bs[k][2j]=Bs[k][2j+1]=B[j][k], so the
// broadcast operand is a natural 64-bit pair (no MOV dups).
template <int MODE>
__global__ void __launch_bounds__(256, 2)
sgemm_tn(const float* __restrict__ A, const float* __restrict__ B,
         const float* __restrict__ bias, float* __restrict__ C,
         int K, int lda, int ldb,
         const float* __restrict__ pvec, const float* __restrict__ shvec)
{
    __shared__ float As[2][8][128];
    __shared__ float Bs[2][8][256];   // duplicated

    const int bx = blockIdx.x, by = blockIdx.y, bz = blockIdx.z;

    const float* Aptr = (MODE == 3) ? (const float*)g_q + (size_t)bz * L_ * D_
                       : (MODE == 4) ? (const float*)g_oh
                       : A;
    const float* Bptr = (MODE == 3) ? (const float*)g_k + (size_t)bz * L_ * D_ : B;

    const int m0 = by * 128, n0 = bx * 128;
    const int t  = threadIdx.x;
    const int tx = t & 15, ty = t >> 4;
    const int lrow = t >> 1;
    const int lcol = (t & 1) * 4;

    const float* Aload = Aptr + (size_t)(m0 + lrow) * lda + lcol;
    const float* Bload = Bptr + (size_t)(n0 + lrow) * ldb + lcol;

    // acc[rp][j]: pair = rows (ty*8+2rp, ty*8+2rp+1), col n0+tx*8+j
    ull acc[4][8];
#pragma unroll
    for (int i = 0; i < 4; i++)
#pragma unroll
        for (int j = 0; j < 8; j++) acc[i][j] = 0ull;

    const int T = K >> 3;

    {   // prologue -> buffer 0
        float4 av = *(const float4*)(Aload);
        float4 bv = *(const float4*)(Bload);
        As[0][lcol + 0][lrow] = av.x; As[0][lcol + 1][lrow] = av.y;
        As[0][lcol + 2][lrow] = av.z; As[0][lcol + 3][lrow] = av.w;
        *(float2*)&Bs[0][lcol + 0][2 * lrow] = make_float2(bv.x, bv.x);
        *(float2*)&Bs[0][lcol + 1][2 * lrow] = make_float2(bv.y, bv.y);
        *(float2*)&Bs[0][lcol + 2][2 * lrow] = make_float2(bv.z, bv.z);
        *(float2*)&Bs[0][lcol + 3][2 * lrow] = make_float2(bv.w, bv.w);
    }
    __syncthreads();

    int cur = 0;
    for (int it = 0; it < T; ++it) {
        float4 av2, bv2;
        const bool more = (it + 1 < T);
        if (more) {
            av2 = *(const float4*)(Aload + (it + 1) * 8);
            bv2 = *(const float4*)(Bload + (it + 1) * 8);
        }
#pragma unroll
        for (int kk = 0; kk < 8; kk++) {
            ulonglong2 a01 = *(const ulonglong2*)&As[cur][kk][ty * 8];
            ulonglong2 a23 = *(const ulonglong2*)&As[cur][kk][ty * 8 + 4];
            ull aa[4] = { a01.x, a01.y, a23.x, a23.y };
            ulonglong2 b0 = *(const ulonglong2*)&Bs[cur][kk][tx * 16];
            ulonglong2 b1 = *(const ulonglong2*)&Bs[cur][kk][tx * 16 + 4];
            ulonglong2 b2 = *(const ulonglong2*)&Bs[cur][kk][tx * 16 + 8];
            ulonglong2 b3 = *(const ulonglong2*)&Bs[cur][kk][tx * 16 + 12];
            ull bb[8] = { b0.x, b0.y, b1.x, b1.y, b2.x, b2.y, b3.x, b3.y };
#pragma unroll
            for (int rp = 0; rp < 4; rp++)
#pragma unroll
                for (int j = 0; j < 8; j++)
                    FMA2(acc[rp][j], aa[rp], bb[j]);
        }
        if (more) {
            const int nxt = cur ^ 1;
            As[nxt][lcol + 0][lrow] = av2.x; As[nxt][lcol + 1][lrow] = av2.y;
            As[nxt][lcol + 2][lrow] = av2.z; As[nxt][lcol + 3][lrow] = av2.w;
            *(float2*)&Bs[nxt][lcol + 0][2 * lrow] = make_float2(bv2.x, bv2.x);
            *(float2*)&Bs[nxt][lcol + 1][2 * lrow] = make_float2(bv2.y, bv2.y);
            *(float2*)&Bs[nxt][lcol + 2][2 * lrow] = make_float2(bv2.z, bv2.z);
            *(float2*)&Bs[nxt][lcol + 3][2 * lrow] = make_float2(bv2.w, bv2.w);
            __syncthreads();
            cur = nxt;
        }
    }

    // ---------------- epilogues ----------------
    if (MODE <= 2) {
        const int ebase = n0 + tx * 8;     // 8-aligned -> single head
        const int h  = ebase >> 6;
        const int d0 = ebase & 63;
        float bb[8], pp[8], ss[8];
#pragma unroll
        for (int j = 0; j < 8; j++) bb[j] = bias[ebase + j];
        if (MODE == 2) {
#pragma unroll
            for (int j = 0; j < 8; j++) { pp[j] = pvec[ebase + j]; ss[j] = shvec[ebase + j]; }
        }
        float* dst = (MODE == 0) ? g_q : (MODE == 1) ? g_k : g_vp;
#pragma unroll
        for (int i = 0; i < 8; i++) {
            int m = m0 + ty * 8 + i;
            int l = m >> 2, n = m & 3;
            float* base = dst + (((size_t)(n * H_ + h) * L_ + l) * D_ + d0);
            float v[8];
#pragma unroll
            for (int j = 0; j < 8; j++) {
                float x = ((i & 1) ? hi2(acc[i >> 1][j]) : lo2(acc[i >> 1][j])) + bb[j];
                if (MODE == 2) x = __powf(fmaxf(x + ss[j], EPS_), pp[j]);
                v[j] = x;
            }
            *(float4*)(base)     = make_float4(v[0], v[1], v[2], v[3]);
            *(float4*)(base + 4) = make_float4(v[4], v[5], v[6], v[7]);
        }
    } else if (MODE == 3) {
        float* dst = g_scores + (size_t)bz * L_ * L_;
#pragma unroll
        for (int i = 0; i < 8; i++) {
            int m = m0 + ty * 8 + i;
            float* base = dst + (size_t)m * L_ + n0 + tx * 8;
            float v[8];
#pragma unroll
            for (int j = 0; j < 8; j++) {
                float x = (i & 1) ? hi2(acc[i >> 1][j]) : lo2(acc[i >> 1][j]);
                v[j] = __expf(0.125f * x);      // unnormalized softmax numerator
            }
            *(float4*)(base)     = make_float4(v[0], v[1], v[2], v[3]);
            *(float4*)(base + 4) = make_float4(v[4], v[5], v[6], v[7]);
        }
    } else {
        const int ebase = n0 + tx * 8;
        float bb[8];
#pragma unroll
        for (int j = 0; j < 8; j++) bb[j] = bias[ebase + j];
#pragma unroll
        for (int i = 0; i < 8; i++) {
            int m = m0 + ty * 8 + i;
            float* base = C + (size_t)m * E_ + ebase;
            float v[8];
#pragma unroll
            for (int j = 0; j < 8; j++)
                v[j] = ((i & 1) ? hi2(acc[i >> 1][j]) : lo2(acc[i >> 1][j])) + bb[j];
            *(float4*)(base)     = make_float4(v[0], v[1], v[2], v[3]);
            *(float4*)(base + 4) = make_float4(v[4], v[5], v[6], v[7]);
        }
    }
}

// pooled = expscores(2048x2048) @ vp(2048x64); accumulates rowsum inline;
// epilogue: divide by rowsum (softmax), GeM inverse -> g_oh.
// Tile: 256 rows x 64 cols, 256 threads, per-thread 16 rows x 4 cols (FMA2 row pairs).
__global__ void __launch_bounds__(256, 2)
pool_gemm(const float* __restrict__ pvec, const float* __restrict__ shvec)
{
    __shared__ float As[2][8][256];
    __shared__ float Bs[2][8][128];   // vp duplicated

    const int by = blockIdx.x;   // m tile 0..7 (256 rows each)
    const int bz = blockIdx.y;   // batch 0..31 (n*8+h)
    const int m0 = by * 256;
    const float* A = g_scores + (size_t)bz * L_ * L_;
    const float* B = g_vp + (size_t)bz * L_ * D_;

    const int t  = threadIdx.x;
    const int tx = t & 15, ty = t >> 4;
    const int kb = t >> 5;            // 0..7
    const int cb = (t & 31) * 2;      // 0..62

    const float* Aload = A + (size_t)(m0 + t) * L_;     // one row per thread
    const float* Bload = B + (size_t)kb * D_ + cb;

    ull acc[8][4];                    // pair = rows (ty*16+2rp, +1), col tx*4+j
    ull rs[8];                        // rowsum pairs
#pragma unroll
    for (int i = 0; i < 8; i++) {
        rs[i] = 0ull;
#pragma unroll
        for (int j = 0; j < 4; j++) acc[i][j] = 0ull;
    }

    {   // prologue -> buffer 0
        float4 a0 = *(const float4*)(Aload);
        float4 a1 = *(const float4*)(Aload + 4);
        As[0][0][t] = a0.x; As[0][1][t] = a0.y; As[0][2][t] = a0.z; As[0][3][t] = a0.w;
        As[0][4][t] = a1.x; As[0][5][t] = a1.y; As[0][6][t] = a1.z; As[0][7][t] = a1.w;
        float2 bv = *(const float2*)(Bload);
        *(float4*)&Bs[0][kb][cb * 2] = make_float4(bv.x, bv.x, bv.y, bv.y);
    }
    __syncthreads();

    int cur = 0;
    const int T = L_ >> 3;   // 256
    for (int it = 0; it < T; ++it) {
        float4 a0n, a1n; float2 bvn;
        const bool more = (it + 1 < T);
        const int k0n = (it + 1) * 8;
        if (more) {
            a0n = *(const float4*)(Aload + k0n);
            a1n = *(const float4*)(Aload + k0n + 4);
            bvn = *(const float2*)(Bload + (size_t)k0n * D_);
        }
#pragma unroll
        for (int kk = 0; kk < 8; kk++) {
            ulonglong2 p0 = *(const ulonglong2*)&As[cur][kk][ty * 16];
            ulonglong2 p1 = *(const ulonglong2*)&As[cur][kk][ty * 16 + 4];
            ulonglong2 p2 = *(const ulonglong2*)&As[cur][kk][ty * 16 + 8];
            ulonglong2 p3 = *(const ulonglong2*)&As[cur][kk][ty * 16 + 12];
            ull aa[8] = { p0.x, p0.y, p1.x, p1.y, p2.x, p2.y, p3.x, p3.y };
            ulonglong2 q0 = *(const ulonglong2*)&Bs[cur][kk][tx * 8];
            ulonglong2 q1 = *(const ulonglong2*)&Bs[cur][kk][tx * 8 + 4];
            ull bb[4] = { q0.x, q0.y, q1.x, q1.y };
#pragma unroll
            for (int rp = 0; rp < 8; rp++) {
                ADD2(rs[rp], aa[rp]);
#pragma unroll
                for (int j = 0; j < 4; j++)
                    FMA2(acc[rp][j], aa[rp], bb[j]);
            }
        }
        if (more) {
            const int nxt = cur ^ 1;
            As[nxt][0][t] = a0n.x; As[nxt][1][t] = a0n.y;
            As[nxt][2][t] = a0n.z; As[nxt][3][t] = a0n.w;
            As[nxt][4][t] = a1n.x; As[nxt][5][t] = a1n.y;
            As[nxt][6][t] = a1n.z; As[nxt][7][t] = a1n.w;
            *(float4*)&Bs[nxt][kb][cb * 2] = make_float4(bvn.x, bvn.x, bvn.y, bvn.y);
            __syncthreads();
            cur = nxt;
        }
    }

    // softmax divide + GeM inverse epilogue
    const int n = bz >> 3, h = bz & 7;
    const int e0 = h * 64 + tx * 4;
    float rp4[4], ss4[4];
#pragma unroll
    for (int j = 0; j < 4; j++) { rp4[j] = 1.0f / pvec[e0 + j]; ss4[j] = shvec[e0 + j]; }
#pragma unroll
    for (int i = 0; i < 16; i++) {
        float rsum = (i & 1) ? hi2(rs[i >> 1]) : lo2(rs[i >> 1]);
        float inv = 1.0f / rsum;
        int l = m0 + ty * 16 + i;
        float v[4];
#pragma unroll
        for (int j = 0; j < 4; j++) {
            float av = ((i & 1) ? hi2(acc[i >> 1][j]) : lo2(acc[i >> 1][j])) * inv;
            v[j] = __powf(fmaxf(av, EPS_), rp4[j]) - ss4[j];
        }
        *(float4*)&g_oh[((size_t)l * NB_ + n) * E_ + e0] = make_float4(v[0], v[1], v[2], v[3]);
    }
}

extern "C" void kernel_launch(void* const* d_in, const int* in_sizes, int n_in,
                              void* d_out, int out_size)
{
    const float* query = (const float*)d_in[0];
    const float* key_  = (const float*)d_in[1];
    const float* value = (const float*)d_in[2];
    const float* wIn   = (const float*)d_in[3];   // (1536, 512)
    const float* bIn   = (const float*)d_in[4];   // (1536,)
    const float* wOut  = (const float*)d_in[5];   // (512, 512)
    const float* bOut  = (const float*)d_in[6];   // (512,)
    const float* p     = (const float*)d_in[7];   // (512,)
    const float* shift = (const float*)d_in[8];   // (512,)
    float* out = (float*)d_out;

    dim3 blk(256);

    // in-projections: (8192x512) @ (512x512)^T
    sgemm_tn<0><<<dim3(4, 64), blk>>>(query, wIn,              bIn,        nullptr,
                                      512, 512, 512, nullptr, nullptr);
    sgemm_tn<1><<<dim3(4, 64), blk>>>(key_,  wIn + 512 * 512,  bIn + 512,  nullptr,
                                      512, 512, 512, nullptr, nullptr);
    sgemm_tn<2><<<dim3(4, 64), blk>>>(value, wIn + 1024 * 512, bIn + 1024, nullptr,
                                      512, 512, 512, p, shift);

    // expscores = exp(q @ k^T / 8), batched over 32 (n,h)
    sgemm_tn<3><<<dim3(16, 16, 32), blk>>>(nullptr, nullptr, nullptr, nullptr,
                                           64, 64, 64, nullptr, nullptr);

    // pooled = softmax @ vp (rowsum inline), GeM inverse -> g_oh
    pool_gemm<<<dim3(8, 32), blk>>>(p, shift);

    // out = oh @ wOut^T + bOut
    sgemm_tn<4><<<dim3(4, 64), blk>>>(nullptr, wOut, bOut, out,
                                      512, 512, 512, nullptr, nullptr);
}

// round 6
// speedup vs baseline: 1.8641x; 1.8641x over previous
#include <cuda_runtime.h>
#include <math.h>

#define L_   2048
#define NB_  4
#define E_   512
#define H_   8
#define D_   64
#define EPS_ 1e-6f

typedef unsigned long long ull;

// ---------------- scratch (static __device__, no allocations) ----------------
__device__ float g_q[(size_t)NB_ * H_ * L_ * D_];        // 16 MB
__device__ float g_k[(size_t)NB_ * H_ * L_ * D_];        // 16 MB
__device__ float g_vp[(size_t)NB_ * H_ * L_ * D_];       // 16 MB  max(v+shift,eps)^p
__device__ float g_scores[(size_t)NB_ * H_ * L_ * L_];   // 512 MB  exp(q.k/8), unnormalized
__device__ float g_oh[(size_t)L_ * NB_ * E_];            // 16 MB  GeM-inverted heads

__device__ __forceinline__ float lo2(ull u) { return __uint_as_float((unsigned)u); }
__device__ __forceinline__ float hi2(ull u) { return __uint_as_float((unsigned)(u >> 32)); }

// packed f32x2 ops (ptxas never emits these from C++)
#define FMA2(d, a, b) asm("fma.rn.f32x2 %0, %1, %2, %0;" : "+l"(d) : "l"(a), "l"(b))
#define ADD2(d, a)    asm("add.rn.f32x2 %0, %1, %0;"     : "+l"(d) : "l"(a))
// swap halves of a packed pair (2x MOV32, lands on alu pipe)
#define SWAP2(d, s)   asm("{\n\t.reg .b32 x, y;\n\tmov.b64 {x, y}, %1;\n\tmov.b64 %0, {y, x};\n\t}" : "=l"(d) : "l"(s))

// diagonal-swap accumulator readout:
//   acc_d[rp][jp]: lo=C[2rp][2jp],   hi=C[2rp+1][2jp+1]
//   acc_x[rp][jp]: lo=C[2rp][2jp+1], hi=C[2rp+1][2jp]
#define ACC_AT(D, X, i, j) \
    (((i) & 1) ? (((j) & 1) ? hi2(D[(i) >> 1][(j) >> 1]) : hi2(X[(i) >> 1][(j) >> 1])) \
               : (((j) & 1) ? lo2(X[(i) >> 1][(j) >> 1]) : lo2(D[(i) >> 1][(j) >> 1])))

// MODE: 0=Q proj, 1=K proj, 2=V proj(+GeM fwd pow), 3=scores exp(qk/8), 4=out proj
// C[m][j] = sum_k A[m][k] * B[j][k]  (TN, row-major).
// FMA2 mainloop, natural (non-duplicated) smem for both operands.
template <int MODE>
__global__ void __launch_bounds__(256, 2)
sgemm_tn(const float* __restrict__ A, const float* __restrict__ B,
         const float* __restrict__ bias, float* __restrict__ C,
         int K, int lda, int ldb,
         const float* __restrict__ pvec, const float* __restrict__ shvec)
{
    __shared__ float As[2][8][128];
    __shared__ float Bs[2][8][128];

    const int bx = blockIdx.x, by = blockIdx.y, bz = blockIdx.z;

    const float* Aptr = (MODE == 3) ? (const float*)g_q + (size_t)bz * L_ * D_
                       : (MODE == 4) ? (const float*)g_oh
                       : A;
    const float* Bptr = (MODE == 3) ? (const float*)g_k + (size_t)bz * L_ * D_ : B;

    const int m0 = by * 128, n0 = bx * 128;
    const int t  = threadIdx.x;
    const int tx = t & 15, ty = t >> 4;
    const int lrow = t >> 1;
    const int lcol = (t & 1) * 4;

    const float* Aload = Aptr + (size_t)(m0 + lrow) * lda + lcol;
    const float* Bload = Bptr + (size_t)(n0 + lrow) * ldb + lcol;

    ull acc_d[4][4], acc_x[4][4];
#pragma unroll
    for (int i = 0; i < 4; i++)
#pragma unroll
        for (int j = 0; j < 4; j++) { acc_d[i][j] = 0ull; acc_x[i][j] = 0ull; }

    const int T = K >> 3;

    {   // prologue -> buffer 0
        float4 av = *(const float4*)(Aload);
        float4 bv = *(const float4*)(Bload);
        As[0][lcol + 0][lrow] = av.x; As[0][lcol + 1][lrow] = av.y;
        As[0][lcol + 2][lrow] = av.z; As[0][lcol + 3][lrow] = av.w;
        Bs[0][lcol + 0][lrow] = bv.x; Bs[0][lcol + 1][lrow] = bv.y;
        Bs[0][lcol + 2][lrow] = bv.z; Bs[0][lcol + 3][lrow] = bv.w;
    }
    __syncthreads();

    int cur = 0;
    for (int it = 0; it < T; ++it) {
        float4 av2, bv2;
        const bool more = (it + 1 < T);
        if (more) {
            av2 = *(const float4*)(Aload + (it + 1) * 8);
            bv2 = *(const float4*)(Bload + (it + 1) * 8);
        }
#pragma unroll
        for (int kk = 0; kk < 8; kk++) {
            ulonglong2 a01 = *(const ulonglong2*)&As[cur][kk][ty * 8];
            ulonglong2 a23 = *(const ulonglong2*)&As[cur][kk][ty * 8 + 4];
            ull aa[4] = { a01.x, a01.y, a23.x, a23.y };
            ulonglong2 b01 = *(const ulonglong2*)&Bs[cur][kk][tx * 8];
            ulonglong2 b23 = *(const ulonglong2*)&Bs[cur][kk][tx * 8 + 4];
            ull bb[4] = { b01.x, b01.y, b23.x, b23.y };
            ull bs[4];
#pragma unroll
            for (int j = 0; j < 4; j++) SWAP2(bs[j], bb[j]);
#pragma unroll
            for (int rp = 0; rp < 4; rp++)
#pragma unroll
                for (int jp = 0; jp < 4; jp++) {
                    FMA2(acc_d[rp][jp], aa[rp], bb[jp]);
                    FMA2(acc_x[rp][jp], aa[rp], bs[jp]);
                }
        }
        if (more) {
            const int nxt = cur ^ 1;
            As[nxt][lcol + 0][lrow] = av2.x; As[nxt][lcol + 1][lrow] = av2.y;
            As[nxt][lcol + 2][lrow] = av2.z; As[nxt][lcol + 3][lrow] = av2.w;
            Bs[nxt][lcol + 0][lrow] = bv2.x; Bs[nxt][lcol + 1][lrow] = bv2.y;
            Bs[nxt][lcol + 2][lrow] = bv2.z; Bs[nxt][lcol + 3][lrow] = bv2.w;
            __syncthreads();
            cur = nxt;
        }
    }

    // ---------------- epilogues ----------------
    if (MODE <= 2) {
        const int ebase = n0 + tx * 8;     // 8-aligned -> single head
        const int h  = ebase >> 6;
        const int d0 = ebase & 63;
        float bb[8], pp[8], ss[8];
#pragma unroll
        for (int j = 0; j < 8; j++) bb[j] = bias[ebase + j];
        if (MODE == 2) {
#pragma unroll
            for (int j = 0; j < 8; j++) { pp[j] = pvec[ebase + j]; ss[j] = shvec[ebase + j]; }
        }
        float* dst = (MODE == 0) ? g_q : (MODE == 1) ? g_k : g_vp;
#pragma unroll
        for (int i = 0; i < 8; i++) {
            int m = m0 + ty * 8 + i;
            int l = m >> 2, n = m & 3;
            float* base = dst + (((size_t)(n * H_ + h) * L_ + l) * D_ + d0);
            float v[8];
#pragma unroll
            for (int j = 0; j < 8; j++) {
                float x = ACC_AT(acc_d, acc_x, i, j) + bb[j];
                if (MODE == 2) x = __powf(fmaxf(x + ss[j], EPS_), pp[j]);
                v[j] = x;
            }
            *(float4*)(base)     = make_float4(v[0], v[1], v[2], v[3]);
            *(float4*)(base + 4) = make_float4(v[4], v[5], v[6], v[7]);
        }
    } else if (MODE == 3) {
        float* dst = g_scores + (size_t)bz * L_ * L_;
#pragma unroll
        for (int i = 0; i < 8; i++) {
            int m = m0 + ty * 8 + i;
            float* base = dst + (size_t)m * L_ + n0 + tx * 8;
            float v[8];
#pragma unroll
            for (int j = 0; j < 8; j++)
                v[j] = __expf(0.125f * ACC_AT(acc_d, acc_x, i, j));   // unnormalized numerator
            *(float4*)(base)     = make_float4(v[0], v[1], v[2], v[3]);
            *(float4*)(base + 4) = make_float4(v[4], v[5], v[6], v[7]);
        }
    } else {
        const int ebase = n0 + tx * 8;
        float bb[8];
#pragma unroll
        for (int j = 0; j < 8; j++) bb[j] = bias[ebase + j];
#pragma unroll
        for (int i = 0; i < 8; i++) {
            int m = m0 + ty * 8 + i;
            float* base = C + (size_t)m * E_ + ebase;
            float v[8];
#pragma unroll
            for (int j = 0; j < 8; j++)
                v[j] = ACC_AT(acc_d, acc_x, i, j) + bb[j];
            *(float4*)(base)     = make_float4(v[0], v[1], v[2], v[3]);
            *(float4*)(base + 4) = make_float4(v[4], v[5], v[6], v[7]);
        }
    }
}

// pooled = expscores(2048x2048) @ vp(2048x64); rowsum accumulated inline;
// epilogue: divide by rowsum (softmax), GeM inverse -> g_oh.
// Tile: 256 rows x 64 cols, 256 threads, thread tile 16x4 (diagonal-swap FMA2).
__global__ void __launch_bounds__(256, 2)
pool_gemm(const float* __restrict__ pvec, const float* __restrict__ shvec)
{
    __shared__ float As[2][8][256];
    __shared__ float Bs[2][8][64];

    const int by = blockIdx.x;   // m tile 0..7 (256 rows each)
    const int bz = blockIdx.y;   // batch 0..31 (n*8+h)
    const int m0 = by * 256;
    const float* A = g_scores + (size_t)bz * L_ * L_;
    const float* B = g_vp + (size_t)bz * L_ * D_;

    const int t  = threadIdx.x;
    const int tx = t & 15, ty = t >> 4;
    const bool bload = (t < 128);
    const int kb = t >> 4;            // 0..7 when t < 128
    const int jc = (t & 15) * 4;

    const float* Aload = A + (size_t)(m0 + t) * L_;     // one row per thread
    const float* Bload = B + (size_t)kb * D_ + jc;

    ull acc_d[8][2], acc_x[8][2];     // 8 row-pairs x 2 col-pairs
    ull rs[8];                        // rowsum pairs
#pragma unroll
    for (int i = 0; i < 8; i++) {
        rs[i] = 0ull;
#pragma unroll
        for (int j = 0; j < 2; j++) { acc_d[i][j] = 0ull; acc_x[i][j] = 0ull; }
    }

    {   // prologue -> buffer 0
        float4 a0 = *(const float4*)(Aload);
        float4 a1 = *(const float4*)(Aload + 4);
        As[0][0][t] = a0.x; As[0][1][t] = a0.y; As[0][2][t] = a0.z; As[0][3][t] = a0.w;
        As[0][4][t] = a1.x; As[0][5][t] = a1.y; As[0][6][t] = a1.z; As[0][7][t] = a1.w;
        if (bload) {
            float4 bv = *(const float4*)(Bload);
            Bs[0][kb][jc + 0] = bv.x; Bs[0][kb][jc + 1] = bv.y;
            Bs[0][kb][jc + 2] = bv.z; Bs[0][kb][jc + 3] = bv.w;
        }
    }
    __syncthreads();

    int cur = 0;
    const int T = L_ >> 3;   // 256
    for (int it = 0; it < T; ++it) {
        float4 a0n, a1n, bvn;
        const bool more = (it + 1 < T);
        const int k0n = (it + 1) * 8;
        if (more) {
            a0n = *(const float4*)(Aload + k0n);
            a1n = *(const float4*)(Aload + k0n + 4);
            if (bload) bvn = *(const float4*)(Bload + (size_t)k0n * D_);
        }
#pragma unroll
        for (int kk = 0; kk < 8; kk++) {
            ulonglong2 p0 = *(const ulonglong2*)&As[cur][kk][ty * 16];
            ulonglong2 p1 = *(const ulonglong2*)&As[cur][kk][ty * 16 + 4];
            ulonglong2 p2 = *(const ulonglong2*)&As[cur][kk][ty * 16 + 8];
            ulonglong2 p3 = *(const ulonglong2*)&As[cur][kk][ty * 16 + 12];
            ull aa[8] = { p0.x, p0.y, p1.x, p1.y, p2.x, p2.y, p3.x, p3.y };
            ulonglong2 q0 = *(const ulonglong2*)&Bs[cur][kk][tx * 4];
            ull bb[2] = { q0.x, q0.y };
            ull bsw[2];
            SWAP2(bsw[0], bb[0]);
            SWAP2(bsw[1], bb[1]);
#pragma unroll
            for (int rp = 0; rp < 8; rp++) {
                ADD2(rs[rp], aa[rp]);
#pragma unroll
                for (int jp = 0; jp < 2; jp++) {
                    FMA2(acc_d[rp][jp], aa[rp], bb[jp]);
                    FMA2(acc_x[rp][jp], aa[rp], bsw[jp]);
                }
            }
        }
        if (more) {
            const int nxt = cur ^ 1;
            As[nxt][0][t] = a0n.x; As[nxt][1][t] = a0n.y;
            As[nxt][2][t] = a0n.z; As[nxt][3][t] = a0n.w;
            As[nxt][4][t] = a1n.x; As[nxt][5][t] = a1n.y;
            As[nxt][6][t] = a1n.z; As[nxt][7][t] = a1n.w;
            if (bload) {
                Bs[nxt][kb][jc + 0] = bvn.x; Bs[nxt][kb][jc + 1] = bvn.y;
                Bs[nxt][kb][jc + 2] = bvn.z; Bs[nxt][kb][jc + 3] = bvn.w;
            }
            __syncthreads();
            cur = nxt;
        }
    }

    // softmax divide + GeM inverse epilogue
    const int n = bz >> 3, h = bz & 7;
    const int e0 = h * 64 + tx * 4;
    float rp4[4], ss4[4];
#pragma unroll
    for (int j = 0; j < 4; j++) { rp4[j] = 1.0f / pvec[e0 + j]; ss4[j] = shvec[e0 + j]; }
#pragma unroll
    for (int i = 0; i < 16; i++) {
        float rsum = (i & 1) ? hi2(rs[i >> 1]) : lo2(rs[i >> 1]);
        float inv = 1.0f / rsum;
        int l = m0 + ty * 16 + i;
        float v[4];
#pragma unroll
        for (int j = 0; j < 4; j++) {
            float av = ACC_AT(acc_d, acc_x, i, j) * inv;
            v[j] = __powf(fmaxf(av, EPS_), rp4[j]) - ss4[j];
        }
        *(float4*)&g_oh[((size_t)l * NB_ + n) * E_ + e0] = make_float4(v[0], v[1], v[2], v[3]);
    }
}

extern "C" void kernel_launch(void* const* d_in, const int* in_sizes, int n_in,
                              void* d_out, int out_size)
{
    const float* query = (const float*)d_in[0];
    const float* key_  = (const float*)d_in[1];
    const float* value = (const float*)d_in[2];
    const float* wIn   = (const float*)d_in[3];   // (1536, 512)
    const float* bIn   = (const float*)d_in[4];   // (1536,)
    const float* wOut  = (const float*)d_in[5];   // (512, 512)
    const float* bOut  = (const float*)d_in[6];   // (512,)
    const float* p     = (const float*)d_in[7];   // (512,)
    const float* shift = (const float*)d_in[8];   // (512,)
    float* out = (float*)d_out;

    dim3 blk(256);

    // in-projections: (8192x512) @ (512x512)^T
    sgemm_tn<0><<<dim3(4, 64), blk>>>(query, wIn,              bIn,        nullptr,
                                      512, 512, 512, nullptr, nullptr);
    sgemm_tn<1><<<dim3(4, 64), blk>>>(key_,  wIn + 512 * 512,  bIn + 512,  nullptr,
                                      512, 512, 512, nullptr, nullptr);
    sgemm_tn<2><<<dim3(4, 64), blk>>>(value, wIn + 1024 * 512, bIn + 1024, nullptr,
                                      512, 512, 512, p, shift);

    // expscores = exp(q @ k^T / 8), batched over 32 (n,h)
    sgemm_tn<3><<<dim3(16, 16, 32), blk>>>(nullptr, nullptr, nullptr, nullptr,
                                           64, 64, 64, nullptr, nullptr);

    // pooled = softmax @ vp (rowsum inline), GeM inverse -> g_oh
    pool_gemm<<<dim3(8, 32), blk>>>(p, shift);

    // out = oh @ wOut^T + bOut
    sgemm_tn<4><<<dim3(4, 64), blk>>>(nullptr, wOut, bOut, out,
                                      512, 512, 512, nullptr, nullptr);
}